// round 6
// baseline (speedup 1.0000x reference)
#include <cuda_runtime.h>
#include <cuda_bf16.h>
#include <cstdint>

#define DIMC  1024
#define NHEAD 16
#define HDIM  64
#define BATCH 2
#define SEQ   2048
#define MROWS (BATCH * SEQ)   // 4096
#define KDIM  1024
#define KCH   32              // bf16 elems per K chunk

// ---------------- scratch (__device__ globals; no allocation allowed) -------
__device__ float g_qh[BATCH * NHEAD * SEQ * HDIM];
__device__ float g_kh[BATCH * NHEAD * SEQ * HDIM];
__device__ float g_vh[BATCH * NHEAD * SEQ * HDIM];
__device__ float g_x [MROWS * DIMC];
__device__ __nv_bfloat16 g_ah[MROWS * DIMC];
__device__ __nv_bfloat16 g_al[MROWS * DIMC];
__device__ __nv_bfloat16 g_wh[3 * DIMC * DIMC];
__device__ __nv_bfloat16 g_wl[3 * DIMC * DIMC];

extern __shared__ char smem_raw[];

// ---------------- PTX helpers (portable ISA only: sm_80+) -------------------
__device__ __forceinline__ uint32_t smem_u32(const void* p) {
    uint32_t a;
    asm("{ .reg .u64 t; cvta.to.shared.u64 t, %1; cvt.u32.u64 %0, t; }" : "=r"(a) : "l"(p));
    return a;
}

#define CP_ASYNC16(dst, src) \
    asm volatile("cp.async.cg.shared.global [%0], [%1], 16;" :: "r"((uint32_t)(dst)), "l"(src))
#define CP_COMMIT() asm volatile("cp.async.commit_group;" ::: "memory")
#define CP_WAIT(n)  asm volatile("cp.async.wait_group %0;" :: "n"(n) : "memory")

__device__ __forceinline__ void ldm_x4(uint32_t* r, uint32_t addr) {
    asm volatile("ldmatrix.sync.aligned.m8n8.x4.shared.b16 {%0,%1,%2,%3}, [%4];"
        : "=r"(r[0]), "=r"(r[1]), "=r"(r[2]), "=r"(r[3]) : "r"(addr));
}
__device__ __forceinline__ void ldm_x2(uint32_t* r, uint32_t addr) {
    asm volatile("ldmatrix.sync.aligned.m8n8.x2.shared.b16 {%0,%1}, [%2];"
        : "=r"(r[0]), "=r"(r[1]) : "r"(addr));
}
__device__ __forceinline__ void mma_bf16(float* c, const uint32_t* a, const uint32_t* b) {
    asm volatile("mma.sync.aligned.m16n8k16.row.col.f32.bf16.bf16.f32 "
        "{%0,%1,%2,%3}, {%4,%5,%6,%7}, {%8,%9}, {%0,%1,%2,%3};"
        : "+f"(c[0]), "+f"(c[1]), "+f"(c[2]), "+f"(c[3])
        : "r"(a[0]), "r"(a[1]), "r"(a[2]), "r"(a[3]), "r"(b[0]), "r"(b[1]));
}

// ---------------- split fp32 -> bf16 hi + lo --------------------------------
__global__ __launch_bounds__(256)
void split_bf16(const float* __restrict__ in, __nv_bfloat16* __restrict__ hi,
                __nv_bfloat16* __restrict__ lo, int n4)
{
    int i = blockIdx.x * 256 + threadIdx.x;
    if (i >= n4) return;
    float4 v = ((const float4*)in)[i];
    float x[4] = {v.x, v.y, v.z, v.w};
    __nv_bfloat16 h[4], l[4];
#pragma unroll
    for (int j = 0; j < 4; ++j) {
        h[j] = __float2bfloat16(x[j]);
        l[j] = __float2bfloat16(x[j] - __bfloat162float(h[j]));
    }
    *(uint2*)(hi + 4 * (size_t)i) = *(const uint2*)h;
    *(uint2*)(lo + 4 * (size_t)i) = *(const uint2*)l;
}

// ---------------- mma.sync bf16x3 GEMM: out[m,n] = sum_k A[m,k]*B[n,k] ------
// 128x128 CTA tile, 8 warps (2m x 4n), each warp 64x32. K chunks of 32,
// 2-stage cp.async pipeline. Rows padded to 40 bf16 (80B) -> conflict-free
// ldmatrix. mode 0: row-major +bias ; mode 1: head-scatter [bh][ns][d].
#define ROWE   40                  // padded row, bf16 elems
#define ROWB   80                  // padded row, bytes
#define MATB   (128 * ROWB)        // 10240 B per matrix tile
#define STAGEB (4 * MATB)          // 40960 B per stage
#define GEMM_SMEM (2 * STAGEB)     // 81920 B

__global__ __launch_bounds__(256)
void gemm_mma(const __nv_bfloat16* __restrict__ Ah, const __nv_bfloat16* __restrict__ Al,
              const __nv_bfloat16* __restrict__ Bh, const __nv_bfloat16* __restrict__ Bl,
              const float* __restrict__ bias, float* __restrict__ out, int mode)
{
    const uint32_t su = smem_u32(smem_raw);
    const int tid  = threadIdx.x;
    const int lane = tid & 31;
    const int warp = tid >> 5;
    const int wm   = warp & 1;          // 0..1 -> 64-row block
    const int wn   = warp >> 1;         // 0..3 -> 32-col block
    const int m0   = blockIdx.y * 128;
    const int n0   = blockIdx.x * 128;

    // global row sources for the 4 matrices (A-side uses m0, B-side n0)
    const int ldrow = tid >> 1;          // 0..127
    const int hsel  = tid & 1;
    const __nv_bfloat16* gsrc[4] = {
        Ah + (size_t)(m0 + ldrow) * KDIM,
        Al + (size_t)(m0 + ldrow) * KDIM,
        Bh + (size_t)(n0 + ldrow) * KDIM,
        Bl + (size_t)(n0 + ldrow) * KDIM
    };

    float c[4][4][4];
#pragma unroll
    for (int mt = 0; mt < 4; ++mt)
#pragma unroll
        for (int nt = 0; nt < 4; ++nt)
#pragma unroll
            for (int f = 0; f < 4; ++f) c[mt][nt][f] = 0.0f;

    const int NCHUNK = KDIM / KCH;   // 32

    // prefetch stage 0
    {
        const uint32_t stg = su;
#pragma unroll
        for (int mx = 0; mx < 4; ++mx) {
            uint32_t dst = stg + mx * MATB + ldrow * ROWB;
            const __nv_bfloat16* gp = gsrc[mx];
#pragma unroll
            for (int cc = 0; cc < 2; ++cc) {
                int chunk = hsel * 2 + cc;
                CP_ASYNC16(dst + chunk * 16, gp + chunk * 8);
            }
        }
        CP_COMMIT();
    }

    for (int ch = 0; ch < NCHUNK; ++ch) {
        const int st = ch & 1;
        if (ch + 1 < NCHUNK) {
            const uint32_t stg = su + ((ch + 1) & 1) * STAGEB;
#pragma unroll
            for (int mx = 0; mx < 4; ++mx) {
                uint32_t dst = stg + mx * MATB + ldrow * ROWB;
                const __nv_bfloat16* gp = gsrc[mx] + (ch + 1) * KCH;
#pragma unroll
                for (int cc = 0; cc < 2; ++cc) {
                    int chunk = hsel * 2 + cc;
                    CP_ASYNC16(dst + chunk * 16, gp + chunk * 8);
                }
            }
            CP_COMMIT();
            CP_WAIT(1);
        } else {
            CP_WAIT(0);
        }
        __syncthreads();

        const uint32_t stg = su + st * STAGEB;
        const int arow = wm * 64 + (lane & 15);
        const int bnrow = wn * 32 + (lane & 7);
#pragma unroll
        for (int kk = 0; kk < 2; ++kk) {
            const int acol = kk * 16 + (lane >> 4) * 8;          // A frag col
            const int bcol = kk * 16 + ((lane >> 3) & 1) * 8;    // B frag col
            uint32_t ah[4][4], al[4][4], bh[4][2], bl[4][2];
#pragma unroll
            for (int mt = 0; mt < 4; ++mt) {
                uint32_t ad = stg + (uint32_t)(arow + mt * 16) * ROWB + acol * 2;
                ldm_x4(ah[mt], ad);
                ldm_x4(al[mt], ad + MATB);
            }
#pragma unroll
            for (int nt = 0; nt < 4; ++nt) {
                uint32_t bd = stg + 2 * MATB + (uint32_t)(bnrow + nt * 8) * ROWB + bcol * 2;
                ldm_x2(bh[nt], bd);
                ldm_x2(bl[nt], bd + MATB);
            }
#pragma unroll
            for (int mt = 0; mt < 4; ++mt)
#pragma unroll
                for (int nt = 0; nt < 4; ++nt) {
                    mma_bf16(c[mt][nt], ah[mt], bh[nt]);
                    mma_bf16(c[mt][nt], ah[mt], bl[nt]);
                    mma_bf16(c[mt][nt], al[mt], bh[nt]);
                }
        }
        __syncthreads();
    }

    // epilogue: frag (T/4 row, (T%4)*2 col pair), rows r and r+8
    const int rw = lane >> 2;
    const int cp2 = (lane & 3) * 2;
#pragma unroll
    for (int mt = 0; mt < 4; ++mt) {
#pragma unroll
        for (int nt = 0; nt < 4; ++nt) {
            int col = n0 + wn * 32 + nt * 8 + cp2;
#pragma unroll
            for (int half = 0; half < 2; ++half) {
                int r = m0 + wm * 64 + mt * 16 + rw + half * 8;
                float v0 = c[mt][nt][half * 2 + 0];
                float v1 = c[mt][nt][half * 2 + 1];
                if (mode == 0) {
                    float2 o = make_float2(v0 + bias[col], v1 + bias[col + 1]);
                    *(float2*)(out + (size_t)r * DIMC + col) = o;
                } else {
                    int b = r >> 11, ns = r & 2047;
                    int h = col >> 6, d = col & 63;
                    float2 o = make_float2(v0, v1);
                    *(float2*)(out + (((size_t)(b * NHEAD + h) * SEQ + ns) * HDIM + d)) = o;
                }
            }
        }
    }
}

// ---------------------------------------------------------------------------
// Fused attention (round-1 proven version).
// ---------------------------------------------------------------------------
__global__ __launch_bounds__(256)
void attn_kernel(const float* __restrict__ qh, const float* __restrict__ kh,
                 const float* __restrict__ vh, float* __restrict__ attn_out,
                 float* __restrict__ xout, const int* __restrict__ umptr)
{
    float* smem = (float*)smem_raw;
    float* sQ = smem;
    float* sK = sQ + 64 * 65;
    float* sV = sK + 64 * 65;
    float* sP = sV + 64 * 65;
    float* sM = sP + 64 * 65;
    float* sL = sM + 64;

    const int tid = threadIdx.x;
    const int qt  = blockIdx.x;
    const int bh  = blockIdx.y;
    const int um  = umptr[0];
    const int q0  = qt * 64;
    const int ty  = tid >> 4;
    const int tx  = tid & 15;
    const float SF = 0.125f * 1.4426950408889634f;

    const float* qb = qh + ((size_t)bh * SEQ + q0) * HDIM;
    const float* kb = kh + (size_t)bh * SEQ * HDIM;
    const float* vb = vh + (size_t)bh * SEQ * HDIM;
    float* ab = attn_out + (size_t)bh * SEQ * SEQ;

#pragma unroll
    for (int l = 0; l < 4; ++l) {
        int id = tid + l * 256;
        int r = id >> 4, c = (id & 15) << 2;
        float4 v = *(const float4*)(qb + r * 64 + c);
        sQ[r * 65 + c + 0] = v.x * SF;
        sQ[r * 65 + c + 1] = v.y * SF;
        sQ[r * 65 + c + 2] = v.z * SF;
        sQ[r * 65 + c + 3] = v.w * SF;
    }
    if (tid < 64) { sM[tid] = -3.0e38f; sL[tid] = 0.0f; }
    __syncthreads();

    const int nkt = um ? (qt + 1) : (SEQ / 64);

    for (int kt = 0; kt < nkt; ++kt) {
#pragma unroll
        for (int l = 0; l < 4; ++l) {
            int id = tid + l * 256;
            int r = id >> 4, c = (id & 15) << 2;
            float4 v = *(const float4*)(kb + (size_t)(kt * 64 + r) * 64 + c);
            sK[r * 65 + c + 0] = v.x;
            sK[r * 65 + c + 1] = v.y;
            sK[r * 65 + c + 2] = v.z;
            sK[r * 65 + c + 3] = v.w;
        }
        __syncthreads();

        float acc[4][4];
#pragma unroll
        for (int i = 0; i < 4; ++i)
#pragma unroll
            for (int j = 0; j < 4; ++j) acc[i][j] = 0.0f;
#pragma unroll 8
        for (int d = 0; d < 64; ++d) {
            float a[4], b[4];
#pragma unroll
            for (int i = 0; i < 4; ++i) a[i] = sQ[(ty * 4 + i) * 65 + d];
#pragma unroll
            for (int j = 0; j < 4; ++j) b[j] = sK[(tx * 4 + j) * 65 + d];
#pragma unroll
            for (int i = 0; i < 4; ++i)
#pragma unroll
                for (int j = 0; j < 4; ++j)
                    acc[i][j] = fmaf(a[i], b[j], acc[i][j]);
        }
        if (um && kt == qt) {
#pragma unroll
            for (int i = 0; i < 4; ++i)
#pragma unroll
                for (int j = 0; j < 4; ++j)
                    if (tx * 4 + j > ty * 4 + i) acc[i][j] = -3.0e9f;
        }
#pragma unroll
        for (int i = 0; i < 4; ++i)
#pragma unroll
            for (int j = 0; j < 4; ++j)
                sP[(ty * 4 + i) * 65 + tx * 4 + j] = acc[i][j];
        __syncthreads();

        if (tid < 64) {
            const float* row = sP + tid * 65;
            float mo = sM[tid];
            float t = -3.0e38f;
#pragma unroll 8
            for (int c = 0; c < 64; ++c) t = fmaxf(t, row[c]);
            float mn = fmaxf(mo, t);
            float s = 0.0f;
#pragma unroll 8
            for (int c = 0; c < 64; ++c) s += exp2f(row[c] - mn);
            sL[tid] = sL[tid] * exp2f(mo - mn) + s;
            sM[tid] = mn;
        }
        __syncthreads();
    }

    if (tid < 64) sL[tid] = 1.0f / sL[tid];
    __syncthreads();

    float accO[4][4];
#pragma unroll
    for (int i = 0; i < 4; ++i)
#pragma unroll
        for (int j = 0; j < 4; ++j) accO[i][j] = 0.0f;

    for (int kt = 0; kt < nkt; ++kt) {
#pragma unroll
        for (int l = 0; l < 4; ++l) {
            int id = tid + l * 256;
            int r = id >> 4, c = (id & 15) << 2;
            float4 v = *(const float4*)(kb + (size_t)(kt * 64 + r) * 64 + c);
            sK[r * 65 + c + 0] = v.x;
            sK[r * 65 + c + 1] = v.y;
            sK[r * 65 + c + 2] = v.z;
            sK[r * 65 + c + 3] = v.w;
            float4 w = *(const float4*)(vb + (size_t)(kt * 64 + r) * 64 + c);
            sV[r * 65 + c + 0] = w.x;
            sV[r * 65 + c + 1] = w.y;
            sV[r * 65 + c + 2] = w.z;
            sV[r * 65 + c + 3] = w.w;
        }
        __syncthreads();

        float acc[4][4];
#pragma unroll
        for (int i = 0; i < 4; ++i)
#pragma unroll
            for (int j = 0; j < 4; ++j) acc[i][j] = 0.0f;
#pragma unroll 8
        for (int d = 0; d < 64; ++d) {
            float a[4], b[4];
#pragma unroll
            for (int i = 0; i < 4; ++i) a[i] = sQ[(ty * 4 + i) * 65 + d];
#pragma unroll
            for (int j = 0; j < 4; ++j) b[j] = sK[(tx * 4 + j) * 65 + d];
#pragma unroll
            for (int i = 0; i < 4; ++i)
#pragma unroll
                for (int j = 0; j < 4; ++j)
                    acc[i][j] = fmaf(a[i], b[j], acc[i][j]);
        }
        if (um && kt == qt) {
#pragma unroll
            for (int i = 0; i < 4; ++i)
#pragma unroll
                for (int j = 0; j < 4; ++j)
                    if (tx * 4 + j > ty * 4 + i) acc[i][j] = -3.0e9f;
        }
#pragma unroll
        for (int i = 0; i < 4; ++i) {
            int r = ty * 4 + i;
            float m = sM[r], il = sL[r];
            float4 p;
            p.x = exp2f(acc[i][0] - m) * il;
            p.y = exp2f(acc[i][1] - m) * il;
            p.z = exp2f(acc[i][2] - m) * il;
            p.w = exp2f(acc[i][3] - m) * il;
            *(float4*)(ab + (size_t)(q0 + r) * SEQ + kt * 64 + tx * 4) = p;
            sP[r * 65 + tx * 4 + 0] = p.x;
            sP[r * 65 + tx * 4 + 1] = p.y;
            sP[r * 65 + tx * 4 + 2] = p.z;
            sP[r * 65 + tx * 4 + 3] = p.w;
        }
        __syncthreads();

#pragma unroll 8
        for (int k = 0; k < 64; ++k) {
            float pa[4], vv[4];
#pragma unroll
            for (int i = 0; i < 4; ++i) pa[i] = sP[(ty * 4 + i) * 65 + k];
#pragma unroll
            for (int j = 0; j < 4; ++j) vv[j] = sV[k * 65 + tx * 4 + j];
#pragma unroll
            for (int i = 0; i < 4; ++i)
#pragma unroll
                for (int j = 0; j < 4; ++j)
                    accO[i][j] = fmaf(pa[i], vv[j], accO[i][j]);
        }
        __syncthreads();
    }

    if (um && nkt < SEQ / 64) {
        int c0 = nkt * 64;
        int nf4 = (SEQ - c0) >> 2;
        float4 z = make_float4(0.f, 0.f, 0.f, 0.f);
        for (int idx = tid; idx < 64 * nf4; idx += 256) {
            int r = idx / nf4;
            int c = c0 + (idx % nf4) * 4;
            *(float4*)(ab + (size_t)(q0 + r) * SEQ + c) = z;
        }
    }

    int b = bh >> 4, h = bh & 15;
#pragma unroll
    for (int i = 0; i < 4; ++i) {
        int r = q0 + ty * 4 + i;
        float4 v = make_float4(accO[i][0], accO[i][1], accO[i][2], accO[i][3]);
        *(float4*)(xout + ((size_t)b * SEQ + r) * DIMC + h * 64 + tx * 4) = v;
    }
}

// ---------------------------------------------------------------------------
extern "C" void kernel_launch(void* const* d_in, const int* in_sizes, int n_in,
                              void* d_out, int out_size)
{
    const float* q      = (const float*)d_in[0];
    const float* k      = (const float*)d_in[1];
    const float* v      = (const float*)d_in[2];
    const float* qkv_w  = (const float*)d_in[3];
    const float* proj_w = (const float*)d_in[4];
    const float* proj_b = (const float*)d_in[5];
    const int*   um     = (const int*)d_in[6];

    float* out      = (float*)d_out;
    float* attn_out = out + (size_t)MROWS * DIMC;

    float *qh, *kh, *vh, *xb;
    __nv_bfloat16 *ah, *al, *wh, *wl;
    cudaGetSymbolAddress((void**)&qh, g_qh);
    cudaGetSymbolAddress((void**)&kh, g_kh);
    cudaGetSymbolAddress((void**)&vh, g_vh);
    cudaGetSymbolAddress((void**)&xb, g_x);
    cudaGetSymbolAddress((void**)&ah, g_ah);
    cudaGetSymbolAddress((void**)&al, g_al);
    cudaGetSymbolAddress((void**)&wh, g_wh);
    cudaGetSymbolAddress((void**)&wl, g_wl);

    cudaFuncSetAttribute(gemm_mma, cudaFuncAttributeMaxDynamicSharedMemorySize, GEMM_SMEM);

    const int NA4 = MROWS * DIMC / 4;
    const int NW4 = 3 * DIMC * DIMC / 4;
    const int NP4 = DIMC * DIMC / 4;

    dim3 ggrid(DIMC / 128, MROWS / 128);    // (8, 32)

    // QKV weight split once
    split_bf16<<<(NW4 + 255) / 256, 256>>>(qkv_w, wh, wl, NW4);

    // Q / K / V projections
    split_bf16<<<(NA4 + 255) / 256, 256>>>(q, ah, al, NA4);
    gemm_mma<<<ggrid, 256, GEMM_SMEM>>>(ah, al, wh, wl, nullptr, qh, 1);
    split_bf16<<<(NA4 + 255) / 256, 256>>>(k, ah, al, NA4);
    gemm_mma<<<ggrid, 256, GEMM_SMEM>>>(ah, al, wh + (size_t)DIMC * DIMC,
                                        wl + (size_t)DIMC * DIMC, nullptr, kh, 1);
    split_bf16<<<(NA4 + 255) / 256, 256>>>(v, ah, al, NA4);
    gemm_mma<<<ggrid, 256, GEMM_SMEM>>>(ah, al, wh + (size_t)2 * DIMC * DIMC,
                                        wl + (size_t)2 * DIMC * DIMC, nullptr, vh, 1);

    // Attention (SIMT, unchanged)
    const int ATTN_SMEM = (4 * 64 * 65 + 128) * (int)sizeof(float);
    cudaFuncSetAttribute(attn_kernel, cudaFuncAttributeMaxDynamicSharedMemorySize, ATTN_SMEM);
    attn_kernel<<<dim3(SEQ / 64, BATCH * NHEAD), 256, ATTN_SMEM>>>(qh, kh, vh, attn_out, xb, um);

    // Output projection
    split_bf16<<<(NA4 + 255) / 256, 256>>>(xb, ah, al, NA4);
    split_bf16<<<(NP4 + 255) / 256, 256>>>(proj_w, wh, wl, NP4);
    gemm_mma<<<ggrid, 256, GEMM_SMEM>>>(ah, al, wh, wl, proj_b, out, 0);
}